// round 12
// baseline (speedup 1.0000x reference)
#include <cuda_runtime.h>

#define BH     32
#define LSEQ   4096
#define D      128
#define C      32
#define NCHUNK 128
#define NSPLIT 4

typedef unsigned long long ull;

// Scratch (device globals are the allowed scratch mechanism)
// g_qt / g_wt are d-pair-interleaved: float idx = chunkbase*128 + d2*64 + c*2 + e
//   value = {q,w}[2*d2 + e][c]   (e in {0,1})
__device__ __align__(16) float g_qt[(size_t)BH * LSEQ * D];
__device__ __align__(16) float g_kn[(size_t)BH * LSEQ * D];   // row-major normalized k
__device__ __align__(16) float g_u [(size_t)BH * LSEQ * D];   // u0 (row-major)
__device__ __align__(16) float g_wt[(size_t)BH * LSEQ * D];
__device__ __align__(16) float g_attn[(size_t)BH * NCHUNK * C * C];  // attn^T: [t][c]

// ---------------------------------------------------------------------------
// f32x2 packed helpers
// ---------------------------------------------------------------------------
__device__ __forceinline__ void fma2(ull& acc, ull a, ull b) {
    asm("fma.rn.f32x2 %0, %1, %2, %0;" : "+l"(acc) : "l"(a), "l"(b));
}
__device__ __forceinline__ void mul2(ull& d, ull a, ull b) {
    asm("mul.rn.f32x2 %0, %1, %2;" : "=l"(d) : "l"(a), "l"(b));
}
__device__ __forceinline__ ull packdup(float s) {
    ull r;
    asm("mov.b64 %0, {%1, %1};" : "=l"(r) : "r"(__float_as_uint(s)));
    return r;
}
__device__ __forceinline__ ull pack2(float lo, float hi) {
    ull r;
    asm("mov.b64 %0, {%1, %2};" : "=l"(r) : "r"(__float_as_uint(lo)), "r"(__float_as_uint(hi)));
    return r;
}
__device__ __forceinline__ void unpack2(ull v, float& lo, float& hi) {
    unsigned a, b;
    asm("mov.b64 {%0, %1}, %2;" : "=r"(a), "=r"(b) : "l"(v));
    lo = __uint_as_float(a); hi = __uint_as_float(b);
}
__device__ __forceinline__ float hadd2(ull v) {
    float lo, hi; unpack2(v, lo, hi); return lo + hi;
}

// ---------------------------------------------------------------------------
// Kernel 1 (fused norm + chunk). 4096 blocks, 128 threads.
// ---------------------------------------------------------------------------
__global__ void chunk_kernel(const float* __restrict__ q,
                             const float* __restrict__ k,
                             const float* __restrict__ v,
                             const float* __restrict__ beta) {
    __shared__ float knT[128 * 33];
    __shared__ float qnT[128 * 33];
    __shared__ float A[32 * 33];
    __shared__ ull   A2s[32 * 32];     // dup-pair copy of A (for f32x2 phase 4)
    __shared__ float beta_s[32];

    int tid = threadIdx.x;
    int lane = tid & 31, wrp = tid >> 5;
    size_t cid = blockIdx.x;
    size_t base = cid * 32;

    // ---- Phase 1: load + l2-normalize (warp per row, 8 rows/warp)
    const float4* q4 = (const float4*)q;
    const float4* k4 = (const float4*)k;
    float4* gkn4 = (float4*)g_kn;
    #pragma unroll
    for (int rr = 0; rr < 8; rr++) {
        int r = wrp * 8 + rr;
        {
            float4 kk = k4[(base + r) * 32 + lane];
            float ss = kk.x * kk.x + kk.y * kk.y + kk.z * kk.z + kk.w * kk.w;
            #pragma unroll
            for (int o = 16; o; o >>= 1) ss += __shfl_xor_sync(0xffffffffu, ss, o);
            float rn = rsqrtf(ss + 1e-6f);
            kk.x *= rn; kk.y *= rn; kk.z *= rn; kk.w *= rn;
            gkn4[(base + r) * 32 + lane] = kk;
            knT[(lane * 4 + 0) * 33 + r] = kk.x;
            knT[(lane * 4 + 1) * 33 + r] = kk.y;
            knT[(lane * 4 + 2) * 33 + r] = kk.z;
            knT[(lane * 4 + 3) * 33 + r] = kk.w;
        }
        {
            float4 qq = q4[(base + r) * 32 + lane];
            float ss = qq.x * qq.x + qq.y * qq.y + qq.z * qq.z + qq.w * qq.w;
            #pragma unroll
            for (int o = 16; o; o >>= 1) ss += __shfl_xor_sync(0xffffffffu, ss, o);
            float rn = rsqrtf(ss + 1e-6f);
            qq.x *= rn; qq.y *= rn; qq.z *= rn; qq.w *= rn;
            qnT[(lane * 4 + 0) * 33 + r] = qq.x;
            qnT[(lane * 4 + 1) * 33 + r] = qq.y;
            qnT[(lane * 4 + 2) * 33 + r] = qq.z;
            qnT[(lane * 4 + 3) * 33 + r] = qq.w;
        }
    }
    if (tid < 32) beta_s[tid] = beta[base + tid];
    __syncthreads();

    int j = lane, iw = wrp;

    // ---- Phase 2: A = -(beta_i * kn_i . kn_j), strictly lower (all warps)
    {
        float acc[8] = {0, 0, 0, 0, 0, 0, 0, 0};
        for (int d = 0; d < 128; d++) {
            float kj = knT[d * 33 + j];
            #pragma unroll
            for (int ii = 0; ii < 8; ii++)
                acc[ii] += knT[d * 33 + (iw * 8 + ii)] * kj;
        }
        #pragma unroll
        for (int ii = 0; ii < 8; ii++) {
            int i = iw * 8 + ii;
            A[i * 33 + j] = (i > j) ? (-beta_s[i] * acc[ii]) : 0.0f;
        }
    }
    __syncthreads();

    // ---- Phase 3 (overlapped): warp 0 -> forward substitution (+ A2 dup store);
    //      warps 1-3 -> attn^T (independent of A) + q^T drain (pair-packed).
    if (wrp == 0) {
        A2s[lane] = 0ull;    // row 0 of A is all zeros
        for (int i = 1; i < 32; i++) {
            float upd = 0.0f;
            for (int t = lane + 1; t < i; t++)
                upd += A[i * 33 + t] * A[t * 33 + lane];
            __syncwarp();
            if (lane < i) A[i * 33 + lane] += upd;
            __syncwarp();
            A2s[i * 32 + lane] = packdup(A[i * 33 + lane]);   // own-lane value
        }
    } else {
        int r0 = (wrp - 1) * 11;
        int nr = (wrp == 3) ? 10 : 11;
        float acc[11];
        #pragma unroll
        for (int ii = 0; ii < 11; ii++) acc[ii] = 0.0f;
        for (int d = 0; d < 128; d++) {
            float qv = qnT[d * 33 + lane];
            #pragma unroll
            for (int ii = 0; ii < 11; ii++)
                if (ii < nr)
                    acc[ii] += knT[d * 33 + (r0 + ii)] * qv;
        }
        float* ga = g_attn + cid * 1024;
        #pragma unroll
        for (int ii = 0; ii < 11; ii++) {
            if (ii < nr) {
                int jr = r0 + ii;
                ga[jr * 32 + lane] = (lane >= jr) ? acc[ii] : 0.0f;
            }
        }
        // q^T drain pair-packed: gq2[d2*32+c] = (q[2d2][c], q[2d2+1][c])
        ull* gq2 = (ull*)(g_qt + base * 128);
        for (int idx = tid - 32; idx < 2048; idx += 96) {
            int d2 = idx >> 5, c = idx & 31;
            gq2[idx] = pack2(qnT[(2 * d2) * 33 + c], qnT[(2 * d2 + 1) * 33 + c]);
        }
    }
    __syncthreads();

    // ---- Phase 4 (f32x2): u = (A+I)@(beta*v) -> g_u; w = (A+I)@(beta*kn) -> staged
    {
        int d32 = lane;                 // 4 cols d32*4..+3 -> 2 ull pairs
        int cw  = wrp;
        const ulonglong2* v2  = (const ulonglong2*)v;
        const ulonglong2* kn2 = (const ulonglong2*)g_kn;
        ull au0[8], au1[8], aw0[8], aw1[8];
        #pragma unroll
        for (int ii = 0; ii < 8; ii++) {
            int c = cw * 8 + ii;
            ulonglong2 vv = v2[(base + c) * 32 + d32];
            ulonglong2 kk = kn2[(base + c) * 32 + d32];
            ull b2 = packdup(beta_s[c]);
            mul2(au0[ii], vv.x, b2); mul2(au1[ii], vv.y, b2);
            mul2(aw0[ii], kk.x, b2); mul2(aw1[ii], kk.y, b2);
        }
        for (int t = 0; t < 32; t++) {
            ulonglong2 vv = v2[(base + t) * 32 + d32];
            ulonglong2 kk = kn2[(base + t) * 32 + d32];
            ull b2 = packdup(beta_s[t]);
            ull vb0, vb1, kb0, kb1;
            mul2(vb0, vv.x, b2); mul2(vb1, vv.y, b2);
            mul2(kb0, kk.x, b2); mul2(kb1, kk.y, b2);
            #pragma unroll
            for (int ii = 0; ii < 8; ii++) {
                ull a2 = A2s[(cw * 8 + ii) * 32 + t];   // LDS.64 broadcast
                fma2(au0[ii], a2, vb0); fma2(au1[ii], a2, vb1);
                fma2(aw0[ii], a2, kb0); fma2(aw1[ii], a2, kb1);
            }
        }
        ulonglong2* gu2 = (ulonglong2*)g_u;
        #pragma unroll
        for (int ii = 0; ii < 8; ii++) {
            int c = cw * 8 + ii;
            ulonglong2 st; st.x = au0[ii]; st.y = au1[ii];
            gu2[(base + c) * 32 + d32] = st;
            float x, y, z, w2;
            unpack2(aw0[ii], x, y);
            unpack2(aw1[ii], z, w2);
            knT[(d32 * 4 + 0) * 33 + c] = x;
            knT[(d32 * 4 + 1) * 33 + c] = y;
            knT[(d32 * 4 + 2) * 33 + c] = z;
            knT[(d32 * 4 + 3) * 33 + c] = w2;
        }
    }
    __syncthreads();
    {   // w drain pair-packed
        ull* gw2 = (ull*)(g_wt + base * 128);
        for (int idx = tid; idx < 2048; idx += 128) {
            int d2 = idx >> 5, c = idx & 31;
            gw2[idx] = pack2(knT[(2 * d2) * 33 + c], knT[(2 * d2 + 1) * 33 + c]);
        }
    }
}

// ---------------------------------------------------------------------------
// cp.async helpers
// ---------------------------------------------------------------------------
__device__ __forceinline__ void cpa16(float* s, const void* g) {
    unsigned a = (unsigned)__cvta_generic_to_shared(s);
    asm volatile("cp.async.cg.shared.global [%0], [%1], 16;" :: "r"(a), "l"(g));
}
__device__ __forceinline__ void cpa_commit() {
    asm volatile("cp.async.commit_group;");
}
__device__ __forceinline__ void cpa_wait_all() {
    asm volatile("cp.async.wait_group 0;");
}

// Scan buffer layout (floats, per buffer):
//   qP[4096] @0, k[4096] @4096, wP[4096] @8192, attnT[1024] @12288
#define OFF_Q    0
#define OFF_K    4096
#define OFF_W    8192
#define OFF_A    12288
#define BUF_FLOATS 13312

// ---------------------------------------------------------------------------
// Kernel 2: sequential scan. grid (NSPLIT, BH), 256 threads.
// S stored pair-interleaved (ull S2[64][32]); warp-owned rows live in registers
// across chunks. Fused w@S/q@S loop uses lane-varying LDS.64 S operands (no dup
// movs). attn@u merged into the S-update c-loop.
// ---------------------------------------------------------------------------
__global__ void __launch_bounds__(256, 1) scan_kernel(float* __restrict__ out) {
    extern __shared__ float sm[];
    ull*   S2 = (ull*)sm;                       // [d2=64][j=32] pairs (16 KB)
    float* us = sm + 4096 + 2 * BUF_FLOATS;     // [c=32][j=32]

    int tid = threadIdx.x;
    int bh = blockIdx.y;
    int dvoff = blockIdx.x * 32;
    int j = tid & 31;              // dv column within slice
    int cg = tid >> 5;             // warp id 0..7: rows c = cg*4 .. cg*4+3

    const float4* gq4 = (const float4*)(g_qt + (size_t)bh * LSEQ * D);
    const float4* gk4 = (const float4*)(g_kn + (size_t)bh * LSEQ * D);
    const float4* gw4 = (const float4*)(g_wt + (size_t)bh * LSEQ * D);
    const float4* ga4 = (const float4*)(g_attn + (size_t)bh * NCHUNK * 1024);
    const float*  gu  = g_u + (size_t)bh * LSEQ * D;
    float* gout = out + (size_t)bh * LSEQ * D + dvoff;

    // ---- prefetch chunk 0 into buffer 0
    {
        float* B = sm + 4096;
        for (int i = tid; i < 1024; i += 256) {
            cpa16(B + OFF_Q + 4 * i, gq4 + i);
            cpa16(B + OFF_K + 4 * i, gk4 + i);
            cpa16(B + OFF_W + 4 * i, gw4 + i);
        }
        cpa16(B + OFF_A + 4 * tid, ga4 + tid);
        cpa_commit();
    }

    for (int i = tid; i < 2048; i += 256) S2[i] = 0ull;

    // warp-owned S rows resident in registers: SP[p] = S2[cg*8+p][j]
    ull SP[8];
    #pragma unroll
    for (int p = 0; p < 8; p++) SP[p] = 0ull;

    for (int ch = 0; ch < NCHUNK; ch++) {
        cpa_wait_all();
        __syncthreads();   // current buffer ready; prev chunk's S2 mirror done

        float* B = sm + 4096 + (ch & 1) * BUF_FLOATS;
        const ulonglong2* qP2 = (const ulonglong2*)(B + OFF_Q);
        const ulonglong2* kk2 = (const ulonglong2*)(B + OFF_K);
        const ulonglong2* wP2 = (const ulonglong2*)(B + OFF_W);
        const ulonglong2* aT2 = (const ulonglong2*)(B + OFF_A);

        // ---- u0 direct LDG, issued early (consumed after fused loop)
        float u00 = gu[(size_t)(ch * 32 + cg * 4 + 0) * 128 + dvoff + j];
        float u01 = gu[(size_t)(ch * 32 + cg * 4 + 1) * 128 + dvoff + j];
        float u02 = gu[(size_t)(ch * 32 + cg * 4 + 2) * 128 + dvoff + j];
        float u03 = gu[(size_t)(ch * 32 + cg * 4 + 3) * 128 + dvoff + j];

        // ---- prefetch chunk ch+1 into the other buffer (overlaps compute)
        if (ch + 1 < NCHUNK) {
            float* P = sm + 4096 + ((ch + 1) & 1) * BUF_FLOATS;
            size_t off4 = (size_t)(ch + 1) * 1024;
            for (int i = tid; i < 1024; i += 256) {
                cpa16(P + OFF_Q + 4 * i, gq4 + off4 + i);
                cpa16(P + OFF_K + 4 * i, gk4 + off4 + i);
                cpa16(P + OFF_W + 4 * i, gw4 + off4 + i);
            }
            cpa16(P + OFF_A + 4 * tid, ga4 + (size_t)(ch + 1) * 256 + tid);
            cpa_commit();
        }

        // ---- fused: MW = w@S, O = q@S, accumulated as (even-d, odd-d) pairs
        ull MW0 = 0, MW1 = 0, MW2 = 0, MW3 = 0;
        ull Oa = 0, Ob = 0, Oc = 0, Od = 0;
        #pragma unroll 4
        for (int d2 = 0; d2 < 64; d2++) {
            ull sv = S2[d2 * 32 + j];                       // lane-varying LDS.64
            ulonglong2 wA = wP2[d2 * 16 + cg * 2];          // pairs for c0,c1
            ulonglong2 wB = wP2[d2 * 16 + cg * 2 + 1];      // c2,c3
            ulonglong2 qA = qP2[d2 * 16 + cg * 2];
            ulonglong2 qB = qP2[d2 * 16 + cg * 2 + 1];
            fma2(MW0, wA.x, sv); fma2(MW1, wA.y, sv);
            fma2(MW2, wB.x, sv); fma2(MW3, wB.y, sv);
            fma2(Oa, qA.x, sv);  fma2(Ob, qA.y, sv);
            fma2(Oc, qB.x, sv);  fma2(Od, qB.y, sv);
        }
        // u_c = u0_c - (even+odd) -> us
        float uc0 = u00 - hadd2(MW0);
        float uc1 = u01 - hadd2(MW1);
        float uc2 = u02 - hadd2(MW2);
        float uc3 = u03 - hadd2(MW3);
        us[(cg * 4 + 0) * 32 + j] = uc0;
        us[(cg * 4 + 1) * 32 + j] = uc1;
        us[(cg * 4 + 2) * 32 + j] = uc2;
        us[(cg * 4 + 3) * 32 + j] = uc3;
        // repack O for the (c0,c1)/(c2,c3)-paired c-loop
        ull O01 = pack2(hadd2(Oa), hadd2(Ob));
        ull O23 = pack2(hadd2(Oc), hadd2(Od));
        __syncthreads();   // us ready; all S2 reads of this chunk complete

        // ---- merged c-loop: O += attn^T u  AND  SP += k^T u (shared us loads)
        #pragma unroll 2
        for (int c = 0; c < 32; c++) {
            ull ud = packdup(us[c * 32 + j]);
            ulonglong2 av = aT2[c * 8 + cg];
            fma2(O01, av.x, ud);
            fma2(O23, av.y, ud);
            #pragma unroll
            for (int qq = 0; qq < 4; qq++) {
                ulonglong2 kv = kk2[c * 32 + cg * 4 + qq];  // k[c][d..d+3] pairs
                fma2(SP[2 * qq + 0], kv.x, ud);
                fma2(SP[2 * qq + 1], kv.y, ud);
            }
        }
        {
            float o0, o1, o2, o3;
            unpack2(O01, o0, o1);
            unpack2(O23, o2, o3);
            gout[(size_t)(ch * 32 + cg * 4 + 0) * 128 + j] = o0;
            gout[(size_t)(ch * 32 + cg * 4 + 1) * 128 + j] = o1;
            gout[(size_t)(ch * 32 + cg * 4 + 2) * 128 + j] = o2;
            gout[(size_t)(ch * 32 + cg * 4 + 3) * 128 + j] = o3;
        }
        // mirror updated warp-owned rows to S2 for other warps' next fused loop
        #pragma unroll
        for (int p = 0; p < 8; p++)
            S2[(cg * 8 + p) * 32 + j] = SP[p];
        // next iteration's top barrier orders these writes before S2 reads
    }
}

// ---------------------------------------------------------------------------
extern "C" void kernel_launch(void* const* d_in, const int* in_sizes, int n_in,
                              void* d_out, int out_size) {
    const float* q    = (const float*)d_in[0];
    const float* k    = (const float*)d_in[1];
    const float* v    = (const float*)d_in[2];
    const float* beta = (const float*)d_in[3];
    float* out = (float*)d_out;

    chunk_kernel<<<BH * NCHUNK, 128>>>(q, k, v, beta);

    const int smem_bytes = (4096 + 2 * BUF_FLOATS + 1024) * sizeof(float); // ~124 KB
    cudaFuncSetAttribute(scan_kernel,
                         cudaFuncAttributeMaxDynamicSharedMemorySize, smem_bytes);
    scan_kernel<<<dim3(NSPLIT, BH), 256, smem_bytes>>>(out);
}